// round 6
// baseline (speedup 1.0000x reference)
#include <cuda_runtime.h>
#include <cuda_bf16.h>
#include <cstdint>

// Decoder LSTM: B=128, H=1024, T from out_size, OUT=1, IN=2.
// Persistent kernel: 128 CTAs, each owns 8 hidden units (32 gate rows of W_hh
// resident in SMEM as bf16 hi/lo). One grid barrier per time step.
// GEMM: gates(128x32) = h(128x1024) @ Wslice^T via mma.m16n8k16 bf16,
// split-precision: Ahi*Whi + Ahi*Wlo + Alo*Whi (fp32 accum) ~ fp32 accuracy.

#define NCTA 128
#define NTHR 256
#define HID 1024
#define BSZ 128
#define KP 1032              // padded K stride (elements) for W in SMEM -> conflict-free B-frag LDS

// SMEM: ws_hi[32*KP] + ws_lo[32*KP] bf16 + 104 floats of per-CTA constants
#define SMEM_BYTES (32 * KP * 2 * 2 + 512)

__device__ __nv_bfloat16 g_h_hi[2][BSZ * HID];
__device__ __nv_bfloat16 g_h_lo[2][BSZ * HID];
__device__ unsigned int g_bar_count = 0;
__device__ unsigned int g_bar_gen = 0;

__device__ __forceinline__ float sigf(float x) {
    return __fdividef(1.0f, 1.0f + __expf(-x));
}
__device__ __forceinline__ float tanh_f(float x) {
    // 2/(1+e^{-2x}) - 1 : saturates cleanly to +-1, no NaN at extremes
    return __fmaf_rn(2.0f, __fdividef(1.0f, 1.0f + __expf(-2.0f * x)), -1.0f);
}

__device__ __forceinline__ void mma_bf16(float* c, const uint32_t* a, uint32_t b0, uint32_t b1) {
    asm volatile(
        "mma.sync.aligned.m16n8k16.row.col.f32.bf16.bf16.f32 "
        "{%0,%1,%2,%3},{%4,%5,%6,%7},{%8,%9},{%0,%1,%2,%3};\n"
        : "+f"(c[0]), "+f"(c[1]), "+f"(c[2]), "+f"(c[3])
        : "r"(a[0]), "r"(a[1]), "r"(a[2]), "r"(a[3]), "r"(b0), "r"(b1));
}

__device__ __forceinline__ void grid_barrier() {
    __threadfence();
    __syncthreads();
    if (threadIdx.x == 0) {
        volatile unsigned int* vgen = &g_bar_gen;
        unsigned int g = *vgen;
        unsigned int arrived = atomicAdd(&g_bar_count, 1u);
        if (arrived == NCTA - 1) {
            g_bar_count = 0;
            __threadfence();
            atomicExch(&g_bar_gen, g + 1u);
        } else {
            while (*vgen == g) { __nanosleep(64); }
        }
        __threadfence();
    }
    __syncthreads();
}

extern __shared__ char smem_raw[];

__global__ __launch_bounds__(NTHR, 1) void decoder_kernel(
    const float* __restrict__ h0, const float* __restrict__ c0,
    const float* __restrict__ Wih, const float* __restrict__ Whh,
    const float* __restrict__ bih, const float* __restrict__ bhh,
    const float* __restrict__ Wlin, const float* __restrict__ blin,
    float* __restrict__ out, int T)
{
    __nv_bfloat16* ws_hi = (__nv_bfloat16*)smem_raw;          // [32][KP]
    __nv_bfloat16* ws_lo = ws_hi + 32 * KP;                   // [32][KP]
    float* cc0 = (float*)(ws_lo + 32 * KP);                   // bias (t=0)
    float* cc1 = cc0 + 32;                                    // bias + Wih[:,1] (t>0)
    float* wi0 = cc1 + 32;                                    // Wih[:,0]
    float* wl  = wi0 + 32;                                    // Wlin slice [8]

    const int j    = blockIdx.x;
    const int tid  = threadIdx.x;
    const int w    = tid >> 5;
    const int lane = tid & 31;
    const int gi   = lane >> 2;   // group id (row within 16-row tile)
    const int tq   = lane & 3;    // thread-in-group (column pair)

    // ---------------- init phase ----------------
    // W_hh slice -> SMEM, split bf16 hi/lo. Local row n = q*8+v maps to
    // global W_hh row q*1024 + 8j + v.
    for (int idx = tid; idx < 32 * HID; idx += NTHR) {
        int n = idx >> 10;
        int k = idx & (HID - 1);
        int row = ((n >> 3) << 10) + (j << 3) + (n & 7);
        float wv = Whh[row * HID + k];
        __nv_bfloat16 hi = __float2bfloat16(wv);
        ws_hi[n * KP + k] = hi;
        ws_lo[n * KP + k] = __float2bfloat16(wv - __bfloat162float(hi));
    }
    if (tid < 32) {
        int n = tid;
        int row = ((n >> 3) << 10) + (j << 3) + (n & 7);
        float bb = bih[row] + bhh[row];
        cc0[n] = bb;
        cc1[n] = bb + Wih[row * 2 + 1];
        wi0[n] = Wih[row * 2 + 0];
    }
    if (tid < 8) wl[tid] = Wlin[(j << 3) + tid];

    // h0 -> bf16 hi/lo buffer 0 (CTA j converts batch row j)
    for (int k = tid; k < HID; k += NTHR) {
        float v = h0[j * HID + k];
        __nv_bfloat16 hi = __float2bfloat16(v);
        g_h_hi[0][j * HID + k] = hi;
        g_h_lo[0][j * HID + k] = __float2bfloat16(v - __bfloat162float(hi));
    }
    // zero output row j (d_out is poisoned; we accumulate into it with atomics)
    for (int t = tid; t < T; t += NTHR) out[j * T + t] = 0.0f;

    // c-state in registers. Thread owns (R0,R0+8) x (v0,v0+1):
    const int R0 = (w << 4) + gi;          // batch rows R0 and R0+8
    const int v0 = tq << 1;                // local hidden v0 and v0+1
    const int u0 = (j << 3) + v0;          // global hidden index
    float creg[4];
    creg[0] = c0[R0 * HID + u0];
    creg[1] = c0[R0 * HID + u0 + 1];
    creg[2] = c0[(R0 + 8) * HID + u0];
    creg[3] = c0[(R0 + 8) * HID + u0 + 1];

    const float blin0 = blin[0];

    grid_barrier();

    const int aoff0 = R0 * (HID / 2) + tq;        // uint32 offsets into h rows
    const int aoff1 = (R0 + 8) * (HID / 2) + tq;

    // ---------------- time loop ----------------
    for (int t = 0; t < T; ++t) {
        const uint32_t* Ahi = (const uint32_t*)g_h_hi[t & 1];
        const uint32_t* Alo = (const uint32_t*)g_h_lo[t & 1];
        __nv_bfloat16* Nhi = g_h_hi[(t + 1) & 1];
        __nv_bfloat16* Nlo = g_h_lo[(t + 1) & 1];

        // accumulator init: bias (+Wih[:,1] for t>0) + out_{t-1} * Wih[:,0]
        float acc[4][4];
        float op0 = 0.0f, op1 = 0.0f;
        const float* cc = cc0;
        if (t > 0) {
            op0 = out[R0 * T + t - 1];
            op1 = out[(R0 + 8) * T + t - 1];
            cc = cc1;
        }
#pragma unroll
        for (int nb = 0; nb < 4; ++nb) {
            int n0 = (nb << 3) + v0;
            float b0 = cc[n0], b1 = cc[n0 + 1];
            float wa = wi0[n0], wb = wi0[n0 + 1];
            acc[nb][0] = fmaf(op0, wa, b0);
            acc[nb][1] = fmaf(op0, wb, b1);
            acc[nb][2] = fmaf(op1, wa, b0);
            acc[nb][3] = fmaf(op1, wb, b1);
        }

        // GEMM over K=1024 with split precision (3 bf16 mma products)
#pragma unroll 2
        for (int kk = 0; kk < HID; kk += 16) {
            uint32_t a_hi[4], a_lo[4];
            int o = kk >> 1;
            a_hi[0] = Ahi[aoff0 + o];
            a_hi[1] = Ahi[aoff1 + o];
            a_hi[2] = Ahi[aoff0 + o + 4];
            a_hi[3] = Ahi[aoff1 + o + 4];
            a_lo[0] = Alo[aoff0 + o];
            a_lo[1] = Alo[aoff1 + o];
            a_lo[2] = Alo[aoff0 + o + 4];
            a_lo[3] = Alo[aoff1 + o + 4];
#pragma unroll
            for (int nb = 0; nb < 4; ++nb) {
                int n = (nb << 3) + gi;
                const uint32_t* bh = (const uint32_t*)(ws_hi + n * KP + kk) + tq;
                const uint32_t* bl = (const uint32_t*)(ws_lo + n * KP + kk) + tq;
                uint32_t bh0 = bh[0], bh1 = bh[4];
                uint32_t bl0 = bl[0], bl1 = bl[4];
                mma_bf16(acc[nb], a_hi, bh0, bh1);
                mma_bf16(acc[nb], a_hi, bl0, bl1);
                mma_bf16(acc[nb], a_lo, bh0, bh1);
            }
        }

        // pointwise LSTM update: all 4 gates for each (R,v) are in this thread
        float s0 = 0.0f, s1 = 0.0f;
#pragma unroll
        for (int ci = 0; ci < 4; ++ci) {
            int rr = ci >> 1;
            int vv = ci & 1;
            float iv = sigf(acc[0][ci]);
            float fv = sigf(acc[1][ci]);
            float gv = tanh_f(acc[2][ci]);
            float ov = sigf(acc[3][ci]);
            float cn = fmaf(fv, creg[ci], iv * gv);
            creg[ci] = cn;
            float hn = ov * tanh_f(cn);
            int R = R0 + (rr << 3);
            int u = u0 + vv;
            __nv_bfloat16 hh = __float2bfloat16(hn);
            Nhi[R * HID + u] = hh;
            Nlo[R * HID + u] = __float2bfloat16(hn - __bfloat162float(hh));
            float contrib = hn * wl[v0 + vv];
            if (rr == 0) s0 += contrib; else s1 += contrib;
        }
        // reduce out-partials over the 4 lanes sharing the same rows
        s0 += __shfl_xor_sync(0xffffffffu, s0, 1);
        s0 += __shfl_xor_sync(0xffffffffu, s0, 2);
        s1 += __shfl_xor_sync(0xffffffffu, s1, 1);
        s1 += __shfl_xor_sync(0xffffffffu, s1, 2);
        if (tq == 0) {
            if (j == 0) { s0 += blin0; s1 += blin0; }
            atomicAdd(&out[R0 * T + t], s0);
            atomicAdd(&out[(R0 + 8) * T + t], s1);
        }

        grid_barrier();
    }
}

extern "C" void kernel_launch(void* const* d_in, const int* in_sizes, int n_in,
                              void* d_out, int out_size) {
    const float* h0   = (const float*)d_in[0];
    const float* c0   = (const float*)d_in[1];
    const float* Wih  = (const float*)d_in[2];
    const float* Whh  = (const float*)d_in[3];
    const float* bih  = (const float*)d_in[4];
    const float* bhh  = (const float*)d_in[5];
    const float* Wlin = (const float*)d_in[6];
    const float* blin = (const float*)d_in[7];
    float* out = (float*)d_out;

    int T = out_size / BSZ;   // (B, T, 1) fp32 output
    if (T <= 0) return;

    cudaFuncSetAttribute(decoder_kernel,
                         cudaFuncAttributeMaxDynamicSharedMemorySize, SMEM_BYTES);
    decoder_kernel<<<NCTA, NTHR, SMEM_BYTES>>>(h0, c0, Wih, Whh, bih, bhh,
                                               Wlin, blin, out, T);
}

// round 7
// speedup vs baseline: 1.9276x; 1.9276x over previous
#include <cuda_runtime.h>
#include <cuda_bf16.h>
#include <cstdint>

// Decoder LSTM: B=128, H=1024, T=256, OUT=1, IN=2.
// Persistent kernel, 128 CTAs x 256 thr. CTA j owns 8 hidden units (32 gate
// rows of W_hh in SMEM, bf16 hi/lo split). One grid barrier per step.
// gates(128x32) = h(128x1024) @ Wslice^T, mma.m16n8k16 bf16, 3-product split.
// h is stored in GLOBAL memory in MMA A-fragment order -> 2x LDG.128 per
// k-iter; B fragments via ldmatrix.x4 -> 4 LDSM per k-iter.

#define NCTA 128
#define NTHR 256
#define HID 1024
#define BSZ 128
#define KP 1032   // padded K stride (bf16 elems) for W in SMEM

#define SMEM_BYTES (32 * KP * 2 * 2 + 512)

// h in A-fragment layout: [tile rt 0..7][tile kt 0..63][lane 0..31][reg 0..3]
__device__ uint32_t g_fhi[2][8 * 64 * 32 * 4];
__device__ uint32_t g_flo[2][8 * 64 * 32 * 4];
__device__ unsigned int g_bar_count = 0;
__device__ unsigned int g_bar_gen = 0;

__device__ __forceinline__ float sigf(float x) {
    return __fdividef(1.0f, 1.0f + __expf(-x));
}
__device__ __forceinline__ float tanh_f(float x) {
    return __fmaf_rn(2.0f, __fdividef(1.0f, 1.0f + __expf(-2.0f * x)), -1.0f);
}

__device__ __forceinline__ void mma_bf16(float* c, const uint4& a, uint32_t b0, uint32_t b1) {
    asm volatile(
        "mma.sync.aligned.m16n8k16.row.col.f32.bf16.bf16.f32 "
        "{%0,%1,%2,%3},{%4,%5,%6,%7},{%8,%9},{%0,%1,%2,%3};\n"
        : "+f"(c[0]), "+f"(c[1]), "+f"(c[2]), "+f"(c[3])
        : "r"(a.x), "r"(a.y), "r"(a.z), "r"(a.w), "r"(b0), "r"(b1));
}

__device__ __forceinline__ void ldsm_x4(uint32_t& r0, uint32_t& r1, uint32_t& r2,
                                        uint32_t& r3, uint32_t saddr) {
    asm volatile("ldmatrix.sync.aligned.m8n8.x4.shared.b16 {%0,%1,%2,%3}, [%4];\n"
                 : "=r"(r0), "=r"(r1), "=r"(r2), "=r"(r3) : "r"(saddr));
}

// split a,b into bf16 hi pair + bf16 lo(residual) pair, packed little-endian
__device__ __forceinline__ void split2(float a, float b, uint32_t& hi, uint32_t& lo) {
    __nv_bfloat16 ha = __float2bfloat16(a), hb = __float2bfloat16(b);
    __nv_bfloat162 H; H.x = ha; H.y = hb;
    hi = *(uint32_t*)&H;
    __nv_bfloat162 L;
    L.x = __float2bfloat16(a - __bfloat162float(ha));
    L.y = __float2bfloat16(b - __bfloat162float(hb));
    lo = *(uint32_t*)&L;
}

__device__ __forceinline__ void grid_barrier() {
    __threadfence();
    __syncthreads();
    if (threadIdx.x == 0) {
        volatile unsigned int* vgen = &g_bar_gen;
        unsigned int g = *vgen;
        unsigned int arrived = atomicAdd(&g_bar_count, 1u);
        if (arrived == NCTA - 1) {
            g_bar_count = 0;
            __threadfence();
            atomicExch(&g_bar_gen, g + 1u);
        } else {
            while (*vgen == g) { __nanosleep(64); }
        }
        __threadfence();
    }
    __syncthreads();
}

extern __shared__ char smem_raw[];

__global__ __launch_bounds__(NTHR, 1) void decoder_kernel(
    const float* __restrict__ h0, const float* __restrict__ c0,
    const float* __restrict__ Wih, const float* __restrict__ Whh,
    const float* __restrict__ bih, const float* __restrict__ bhh,
    const float* __restrict__ Wlin, const float* __restrict__ blin,
    float* __restrict__ out, int T)
{
    __nv_bfloat16* ws_hi = (__nv_bfloat16*)smem_raw;   // [32][KP]
    __nv_bfloat16* ws_lo = ws_hi + 32 * KP;            // [32][KP]
    float* cc0 = (float*)(ws_lo + 32 * KP);            // bias (t=0)
    float* cc1 = cc0 + 32;                             // bias + Wih[:,1]
    float* wi0 = cc1 + 32;                             // Wih[:,0]
    float* wl  = wi0 + 32;                             // Wlin slice [8]

    const int j    = blockIdx.x;
    const int tid  = threadIdx.x;
    const int w    = tid >> 5;
    const int lane = tid & 31;
    const int gi   = lane >> 2;
    const int tq   = lane & 3;

    // ---------------- init: W slice -> SMEM hi/lo ----------------
    for (int idx = tid; idx < 32 * HID; idx += NTHR) {
        int n = idx >> 10;
        int k = idx & (HID - 1);
        int row = ((n >> 3) << 10) + (j << 3) + (n & 7);
        float wv = Whh[row * HID + k];
        __nv_bfloat16 hi = __float2bfloat16(wv);
        ws_hi[n * KP + k] = hi;
        ws_lo[n * KP + k] = __float2bfloat16(wv - __bfloat162float(hi));
    }
    if (tid < 32) {
        int n = tid;
        int row = ((n >> 3) << 10) + (j << 3) + (n & 7);
        float bb = bih[row] + bhh[row];
        cc0[n] = bb;
        cc1[n] = bb + Wih[row * 2 + 1];
        wi0[n] = Wih[row * 2 + 0];
    }
    if (tid < 8) wl[tid] = Wlin[(j << 3) + tid];

    // h0 -> fragment-layout buffer 0 (CTA j converts batch row j)
    for (int p = tid; p < HID / 2; p += NTHR) {
        int k0 = p << 1;
        float v0 = h0[j * HID + k0], v1 = h0[j * HID + k0 + 1];
        int rt = j >> 4, kt = k0 >> 4;
        int lanep = (j & 7) * 4 + ((k0 >> 1) & 3);
        int reg = ((j >> 3) & 1) + 2 * ((k0 >> 3) & 1);
        int idx = ((rt * 64 + kt) * 32 + lanep) * 4 + reg;
        uint32_t hi, lo;
        split2(v0, v1, hi, lo);
        g_fhi[0][idx] = hi;
        g_flo[0][idx] = lo;
    }
    for (int t = tid; t < T; t += NTHR) out[j * T + t] = 0.0f;

    // c-state in registers: thread owns (R0,R0+8) x (u0,u0+1)
    const int R0 = (w << 4) + gi;
    const int v0 = tq << 1;
    const int u0 = (j << 3) + v0;
    float creg[4];
    creg[0] = c0[R0 * HID + u0];
    creg[1] = c0[R0 * HID + u0 + 1];
    creg[2] = c0[(R0 + 8) * HID + u0];
    creg[3] = c0[(R0 + 8) * HID + u0 + 1];

    const float blin0 = blin[0];

    // ldmatrix per-lane base addresses (4 matrices: {nb, nb+1} x {k, k+8})
    const int m_   = lane >> 3;                 // matrix index 0..3
    const int rr_  = lane & 7;
    const int nloc = ((m_ >> 1) << 3) + rr_;    // W local row for this lane
    const int koff = (m_ & 1) << 3;
    const uint32_t s_hi = (uint32_t)__cvta_generic_to_shared(ws_hi);
    const uint32_t s_lo = (uint32_t)__cvta_generic_to_shared(ws_lo);
    const uint32_t sb_hi01 = s_hi + (nloc * KP + koff) * 2;
    const uint32_t sb_hi23 = sb_hi01 + 16 * KP * 2;
    const uint32_t sb_lo01 = s_lo + (nloc * KP + koff) * 2;
    const uint32_t sb_lo23 = sb_lo01 + 16 * KP * 2;

    const int abase = w * 8192 + lane * 4;      // uint32 index into fragment buf
    const int wbase = ((w * 64 + (j >> 1)) * 32 + lane) * 4 + 2 * (j & 1);

    grid_barrier();

    // ---------------- time loop ----------------
    for (int t = 0; t < T; ++t) {
        const uint32_t* Ahi = g_fhi[t & 1];
        const uint32_t* Alo = g_flo[t & 1];
        uint32_t* Nhi = g_fhi[(t + 1) & 1];
        uint32_t* Nlo = g_flo[(t + 1) & 1];

        // acc init: bias (+Wih[:,1] for t>0) + out_{t-1} * Wih[:,0]
        float acc[4][4];
        float op0 = 0.0f, op1 = 0.0f;
        const float* cc = cc0;
        if (t > 0) {
            op0 = __ldcg(&out[R0 * T + t - 1]);
            op1 = __ldcg(&out[(R0 + 8) * T + t - 1]);
            cc = cc1;
        }
#pragma unroll
        for (int nb = 0; nb < 4; ++nb) {
            int n0 = (nb << 3) + v0;
            float b0 = cc[n0], b1 = cc[n0 + 1];
            float wa = wi0[n0], wb = wi0[n0 + 1];
            acc[nb][0] = fmaf(op0, wa, b0);
            acc[nb][1] = fmaf(op0, wb, b1);
            acc[nb][2] = fmaf(op1, wa, b0);
            acc[nb][3] = fmaf(op1, wb, b1);
        }

        // GEMM: K=1024, 16 per iter, 3-product bf16 split
#pragma unroll 4
        for (int kt = 0; kt < 64; ++kt) {
            uint4 ah = __ldcg((const uint4*)(Ahi + abase + kt * 128));
            uint4 al = __ldcg((const uint4*)(Alo + abase + kt * 128));
            uint32_t so = kt * 32;
            uint32_t bh0, bh1, bh2, bh3, bh4, bh5, bh6, bh7;
            uint32_t bl0, bl1, bl2, bl3, bl4, bl5, bl6, bl7;
            ldsm_x4(bh0, bh1, bh2, bh3, sb_hi01 + so);
            ldsm_x4(bh4, bh5, bh6, bh7, sb_hi23 + so);
            ldsm_x4(bl0, bl1, bl2, bl3, sb_lo01 + so);
            ldsm_x4(bl4, bl5, bl6, bl7, sb_lo23 + so);
            mma_bf16(acc[0], ah, bh0, bh1);
            mma_bf16(acc[0], al, bh0, bh1);
            mma_bf16(acc[0], ah, bl0, bl1);
            mma_bf16(acc[1], ah, bh2, bh3);
            mma_bf16(acc[1], al, bh2, bh3);
            mma_bf16(acc[1], ah, bl2, bl3);
            mma_bf16(acc[2], ah, bh4, bh5);
            mma_bf16(acc[2], al, bh4, bh5);
            mma_bf16(acc[2], ah, bl4, bl5);
            mma_bf16(acc[3], ah, bh6, bh7);
            mma_bf16(acc[3], al, bh6, bh7);
            mma_bf16(acc[3], ah, bl6, bl7);
        }

        // pointwise LSTM update (all 4 gates local to this thread)
        float hn[4];
        float s0 = 0.0f, s1 = 0.0f;
#pragma unroll
        for (int ci = 0; ci < 4; ++ci) {
            float iv = sigf(acc[0][ci]);
            float fv = sigf(acc[1][ci]);
            float gv = tanh_f(acc[2][ci]);
            float ov = sigf(acc[3][ci]);
            float cn = fmaf(fv, creg[ci], iv * gv);
            creg[ci] = cn;
            float h = ov * tanh_f(cn);
            hn[ci] = h;
            float contrib = h * wl[v0 + (ci & 1)];
            if (ci < 2) s0 += contrib; else s1 += contrib;
        }
        // store h_{t+1} in fragment layout: one STG.64 per buffer
        uint32_t phi0, plo0, phi1, plo1;
        split2(hn[0], hn[1], phi0, plo0);   // row R0
        split2(hn[2], hn[3], phi1, plo1);   // row R0+8
        *(uint2*)(Nhi + wbase) = make_uint2(phi0, phi1);
        *(uint2*)(Nlo + wbase) = make_uint2(plo0, plo1);

        // reduce the scalar head over 4 lanes sharing the same rows
        s0 += __shfl_xor_sync(0xffffffffu, s0, 1);
        s0 += __shfl_xor_sync(0xffffffffu, s0, 2);
        s1 += __shfl_xor_sync(0xffffffffu, s1, 1);
        s1 += __shfl_xor_sync(0xffffffffu, s1, 2);
        if (tq == 0) {
            if (j == 0) { s0 += blin0; s1 += blin0; }
            atomicAdd(&out[R0 * T + t], s0);
            atomicAdd(&out[(R0 + 8) * T + t], s1);
        }

        grid_barrier();
    }
}

extern "C" void kernel_launch(void* const* d_in, const int* in_sizes, int n_in,
                              void* d_out, int out_size) {
    const float* h0   = (const float*)d_in[0];
    const float* c0   = (const float*)d_in[1];
    const float* Wih  = (const float*)d_in[2];
    const float* Whh  = (const float*)d_in[3];
    const float* bih  = (const float*)d_in[4];
    const float* bhh  = (const float*)d_in[5];
    const float* Wlin = (const float*)d_in[6];
    const float* blin = (const float*)d_in[7];
    float* out = (float*)d_out;

    int T = out_size / BSZ;
    if (T <= 0) return;

    cudaFuncSetAttribute(decoder_kernel,
                         cudaFuncAttributeMaxDynamicSharedMemorySize, SMEM_BYTES);
    decoder_kernel<<<NCTA, NTHR, SMEM_BYTES>>>(h0, c0, Wih, Whh, bih, bhh,
                                               Wlin, blin, out, T);
}

// round 8
// speedup vs baseline: 2.0903x; 1.0844x over previous
#include <cuda_runtime.h>
#include <cuda_bf16.h>
#include <cstdint>

// Decoder LSTM: B=128, H=1024, T=256, OUT=1, IN=2.
// Persistent kernel, 128 CTAs x 512 thr (16 warps). CTA j owns 8 hidden units
// (32 gate rows of W_hh in SMEM, bf16 hi/lo split). One grid barrier per step.
// gates(128x32) = h(128x1024) @ Wslice^T, mma.m16n8k16 bf16, 3-product split.
// K-split: warp pair (w, w+8) shares an rt tile; each does 32 of 64 k-tiles;
// partials merged through SMEM. h lives in global in A-fragment order
// (2x LDG.128 per k-iter); B fragments via ldmatrix.x4.

#define NCTA 128
#define NTHR 512
#define HID 1024
#define BSZ 128
#define KP 1032   // padded K stride (bf16 elems) for W in SMEM

#define W_BYTES (32 * KP * 2 * 2)
#define RED_BYTES (8 * 32 * 16 * 4)
#define SMEM_BYTES (W_BYTES + 512 + RED_BYTES)

// h in A-fragment layout: [rt 0..7][kt 0..63][lane 0..31][reg 0..3]
__device__ uint32_t g_fhi[2][8 * 64 * 32 * 4];
__device__ uint32_t g_flo[2][8 * 64 * 32 * 4];
__device__ unsigned int g_bar_count = 0;
__device__ unsigned int g_bar_gen = 0;

__device__ __forceinline__ float sigf(float x) {
    return __fdividef(1.0f, 1.0f + __expf(-x));
}
__device__ __forceinline__ float tanh_f(float x) {
    return __fmaf_rn(2.0f, __fdividef(1.0f, 1.0f + __expf(-2.0f * x)), -1.0f);
}

__device__ __forceinline__ void mma_bf16(float* c, const uint4& a, uint32_t b0, uint32_t b1) {
    asm volatile(
        "mma.sync.aligned.m16n8k16.row.col.f32.bf16.bf16.f32 "
        "{%0,%1,%2,%3},{%4,%5,%6,%7},{%8,%9},{%0,%1,%2,%3};\n"
        : "+f"(c[0]), "+f"(c[1]), "+f"(c[2]), "+f"(c[3])
        : "r"(a.x), "r"(a.y), "r"(a.z), "r"(a.w), "r"(b0), "r"(b1));
}

__device__ __forceinline__ void ldsm_x4(uint32_t& r0, uint32_t& r1, uint32_t& r2,
                                        uint32_t& r3, uint32_t saddr) {
    asm volatile("ldmatrix.sync.aligned.m8n8.x4.shared.b16 {%0,%1,%2,%3}, [%4];\n"
                 : "=r"(r0), "=r"(r1), "=r"(r2), "=r"(r3) : "r"(saddr));
}

__device__ __forceinline__ void split2(float a, float b, uint32_t& hi, uint32_t& lo) {
    __nv_bfloat16 ha = __float2bfloat16(a), hb = __float2bfloat16(b);
    __nv_bfloat162 H; H.x = ha; H.y = hb;
    hi = *(uint32_t*)&H;
    __nv_bfloat162 L;
    L.x = __float2bfloat16(a - __bfloat162float(ha));
    L.y = __float2bfloat16(b - __bfloat162float(hb));
    lo = *(uint32_t*)&L;
}

__device__ __forceinline__ void grid_barrier() {
    __threadfence();
    __syncthreads();
    if (threadIdx.x == 0) {
        volatile unsigned int* vgen = &g_bar_gen;
        unsigned int g = *vgen;
        unsigned int arrived = atomicAdd(&g_bar_count, 1u);
        if (arrived == NCTA - 1) {
            g_bar_count = 0;
            __threadfence();
            atomicExch(&g_bar_gen, g + 1u);
        } else {
            while (*vgen == g) {}
        }
        __threadfence();
    }
    __syncthreads();
}

extern __shared__ char smem_raw[];

__global__ __launch_bounds__(NTHR, 1) void decoder_kernel(
    const float* __restrict__ h0, const float* __restrict__ c0,
    const float* __restrict__ Wih, const float* __restrict__ Whh,
    const float* __restrict__ bih, const float* __restrict__ bhh,
    const float* __restrict__ Wlin, const float* __restrict__ blin,
    float* __restrict__ out, int T)
{
    __nv_bfloat16* ws_hi = (__nv_bfloat16*)smem_raw;   // [32][KP]
    __nv_bfloat16* ws_lo = ws_hi + 32 * KP;            // [32][KP]
    float* cc0 = (float*)(smem_raw + W_BYTES);         // bias (t=0)
    float* cc1 = cc0 + 32;                             // bias + Wih[:,1]
    float* wi0 = cc1 + 32;                             // Wih[:,0]
    float* wl  = wi0 + 32;                             // Wlin slice [8]
    float* red = (float*)(smem_raw + W_BYTES + 512);   // [8][32][16] partials

    const int j    = blockIdx.x;
    const int tid  = threadIdx.x;
    const int w    = tid >> 5;
    const int wk   = w & 7;      // rt tile
    const int ks   = w >> 3;     // k-split half (0 or 1)
    const int lane = tid & 31;
    const int gi   = lane >> 2;
    const int tq   = lane & 3;

    // ---------------- init: W slice -> SMEM hi/lo ----------------
    for (int idx = tid; idx < 32 * HID; idx += NTHR) {
        int n = idx >> 10;
        int k = idx & (HID - 1);
        int row = ((n >> 3) << 10) + (j << 3) + (n & 7);
        float wv = Whh[row * HID + k];
        __nv_bfloat16 hi = __float2bfloat16(wv);
        ws_hi[n * KP + k] = hi;
        ws_lo[n * KP + k] = __float2bfloat16(wv - __bfloat162float(hi));
    }
    if (tid < 32) {
        int n = tid;
        int row = ((n >> 3) << 10) + (j << 3) + (n & 7);
        float bb = bih[row] + bhh[row];
        cc0[n] = bb;
        cc1[n] = bb + Wih[row * 2 + 1];
        wi0[n] = Wih[row * 2 + 0];
    }
    if (tid < 8) wl[tid] = Wlin[(j << 3) + tid];

    // h0 -> fragment-layout buffer 0 (CTA j converts batch row j)
    for (int p = tid; p < HID / 2; p += NTHR) {
        int k0 = p << 1;
        float v0 = h0[j * HID + k0], v1 = h0[j * HID + k0 + 1];
        int rt = j >> 4, kt = k0 >> 4;
        int lanep = (j & 7) * 4 + ((k0 >> 1) & 3);
        int reg = ((j >> 3) & 1) + 2 * ((k0 >> 3) & 1);
        int idx = ((rt * 64 + kt) * 32 + lanep) * 4 + reg;
        uint32_t hi, lo;
        split2(v0, v1, hi, lo);
        g_fhi[0][idx] = hi;
        g_flo[0][idx] = lo;
    }
    for (int t = tid; t < T; t += NTHR) out[j * T + t] = 0.0f;

    // c-state in registers (pointwise warps ks==0 only)
    const int R0 = (wk << 4) + gi;
    const int v0 = tq << 1;
    const int u0 = (j << 3) + v0;
    float creg[4] = {0.f, 0.f, 0.f, 0.f};
    if (ks == 0) {
        creg[0] = c0[R0 * HID + u0];
        creg[1] = c0[R0 * HID + u0 + 1];
        creg[2] = c0[(R0 + 8) * HID + u0];
        creg[3] = c0[(R0 + 8) * HID + u0 + 1];
    }
    const float blin0 = blin[0];

    // ldmatrix per-lane base addresses (4 matrices: {nb,nb+1} x {k,k+8})
    const int m_   = lane >> 3;
    const int rr_  = lane & 7;
    const int nloc = ((m_ >> 1) << 3) + rr_;
    const int koff = (m_ & 1) << 3;
    const uint32_t s_hi = (uint32_t)__cvta_generic_to_shared(ws_hi);
    const uint32_t s_lo = (uint32_t)__cvta_generic_to_shared(ws_lo);
    const uint32_t sb_hi01 = s_hi + (nloc * KP + koff) * 2;
    const uint32_t sb_hi23 = sb_hi01 + 16 * KP * 2;
    const uint32_t sb_lo01 = s_lo + (nloc * KP + koff) * 2;
    const uint32_t sb_lo23 = sb_lo01 + 16 * KP * 2;

    const int kt0   = ks << 5;                       // this warp's k range start
    const int abase = wk * 8192 + kt0 * 128 + lane * 4;
    const int wbase = ((wk * 64 + (j >> 1)) * 32 + lane) * 4 + 2 * (j & 1);
    float* redp = red + (wk * 32 + lane) * 16;

    grid_barrier();

    // ---------------- time loop ----------------
    for (int t = 0; t < T; ++t) {
        const uint32_t* Ahi = g_fhi[t & 1];
        const uint32_t* Alo = g_flo[t & 1];
        uint32_t* Nhi = g_fhi[(t + 1) & 1];
        uint32_t* Nlo = g_flo[(t + 1) & 1];

        // acc init: warps ks==0 carry bias + feedback; ks==1 carry zeros
        float acc[4][4];
        if (ks == 0) {
            float op0 = 0.0f, op1 = 0.0f;
            const float* cc = cc0;
            if (t > 0) {
                op0 = __ldcg(&out[R0 * T + t - 1]);
                op1 = __ldcg(&out[(R0 + 8) * T + t - 1]);
                cc = cc1;
            }
#pragma unroll
            for (int nb = 0; nb < 4; ++nb) {
                int n0 = (nb << 3) + v0;
                float b0 = cc[n0], b1 = cc[n0 + 1];
                float wa = wi0[n0], wb = wi0[n0 + 1];
                acc[nb][0] = fmaf(op0, wa, b0);
                acc[nb][1] = fmaf(op0, wb, b1);
                acc[nb][2] = fmaf(op1, wa, b0);
                acc[nb][3] = fmaf(op1, wb, b1);
            }
        } else {
#pragma unroll
            for (int nb = 0; nb < 4; ++nb)
#pragma unroll
                for (int c = 0; c < 4; ++c) acc[nb][c] = 0.0f;
        }

        // GEMM: this warp's 32 k-tiles, 3-product bf16 split
#pragma unroll 4
        for (int i = 0; i < 32; ++i) {
            uint4 ah = __ldcg((const uint4*)(Ahi + abase + i * 128));
            uint4 al = __ldcg((const uint4*)(Alo + abase + i * 128));
            uint32_t so = (kt0 + i) * 32;
            uint32_t bh0, bh1, bh2, bh3, bh4, bh5, bh6, bh7;
            uint32_t bl0, bl1, bl2, bl3, bl4, bl5, bl6, bl7;
            ldsm_x4(bh0, bh1, bh2, bh3, sb_hi01 + so);
            ldsm_x4(bh4, bh5, bh6, bh7, sb_hi23 + so);
            ldsm_x4(bl0, bl1, bl2, bl3, sb_lo01 + so);
            ldsm_x4(bl4, bl5, bl6, bl7, sb_lo23 + so);
            mma_bf16(acc[0], ah, bh0, bh1);
            mma_bf16(acc[0], al, bh0, bh1);
            mma_bf16(acc[0], ah, bl0, bl1);
            mma_bf16(acc[1], ah, bh2, bh3);
            mma_bf16(acc[1], al, bh2, bh3);
            mma_bf16(acc[1], ah, bl2, bl3);
            mma_bf16(acc[2], ah, bh4, bh5);
            mma_bf16(acc[2], al, bh4, bh5);
            mma_bf16(acc[2], ah, bl4, bl5);
            mma_bf16(acc[3], ah, bh6, bh7);
            mma_bf16(acc[3], al, bh6, bh7);
            mma_bf16(acc[3], ah, bl6, bl7);
        }

        // merge k-split partials through SMEM
        if (ks == 1) {
#pragma unroll
            for (int nb = 0; nb < 4; ++nb)
#pragma unroll
                for (int c = 0; c < 4; ++c) redp[nb * 4 + c] = acc[nb][c];
        }
        __syncthreads();

        if (ks == 0) {
#pragma unroll
            for (int nb = 0; nb < 4; ++nb)
#pragma unroll
                for (int c = 0; c < 4; ++c) acc[nb][c] += redp[nb * 4 + c];

            // pointwise LSTM update (all 4 gates local to this thread)
            float hn[4];
            float s0 = 0.0f, s1 = 0.0f;
#pragma unroll
            for (int ci = 0; ci < 4; ++ci) {
                float iv = sigf(acc[0][ci]);
                float fv = sigf(acc[1][ci]);
                float gv = tanh_f(acc[2][ci]);
                float ov = sigf(acc[3][ci]);
                float cn = fmaf(fv, creg[ci], iv * gv);
                creg[ci] = cn;
                float h = ov * tanh_f(cn);
                hn[ci] = h;
                float contrib = h * wl[v0 + (ci & 1)];
                if (ci < 2) s0 += contrib; else s1 += contrib;
            }
            uint32_t phi0, plo0, phi1, plo1;
            split2(hn[0], hn[1], phi0, plo0);
            split2(hn[2], hn[3], phi1, plo1);
            *(uint2*)(Nhi + wbase) = make_uint2(phi0, phi1);
            *(uint2*)(Nlo + wbase) = make_uint2(plo0, plo1);

            s0 += __shfl_xor_sync(0xffffffffu, s0, 1);
            s0 += __shfl_xor_sync(0xffffffffu, s0, 2);
            s1 += __shfl_xor_sync(0xffffffffu, s1, 1);
            s1 += __shfl_xor_sync(0xffffffffu, s1, 2);
            if (tq == 0) {
                if (j == 0) { s0 += blin0; s1 += blin0; }
                atomicAdd(&out[R0 * T + t], s0);
                atomicAdd(&out[(R0 + 8) * T + t], s1);
            }
        }

        grid_barrier();
    }
}

extern "C" void kernel_launch(void* const* d_in, const int* in_sizes, int n_in,
                              void* d_out, int out_size) {
    const float* h0   = (const float*)d_in[0];
    const float* c0   = (const float*)d_in[1];
    const float* Wih  = (const float*)d_in[2];
    const float* Whh  = (const float*)d_in[3];
    const float* bih  = (const float*)d_in[4];
    const float* bhh  = (const float*)d_in[5];
    const float* Wlin = (const float*)d_in[6];
    const float* blin = (const float*)d_in[7];
    float* out = (float*)d_out;

    int T = out_size / BSZ;
    if (T <= 0) return;

    cudaFuncSetAttribute(decoder_kernel,
                         cudaFuncAttributeMaxDynamicSharedMemorySize, SMEM_BYTES);
    decoder_kernel<<<NCTA, NTHR, SMEM_BYTES>>>(h0, c0, Wih, Whh, bih, bhh,
                                               Wlin, blin, out, T);
}

// round 9
// speedup vs baseline: 2.6827x; 1.2834x over previous
#include <cuda_runtime.h>
#include <cuda_fp16.h>
#include <cstdint>

// Decoder LSTM: B=128, H=1024, T=256, OUT=1, IN=2.
// Persistent kernel, 128 CTAs x 512 thr (16 warps). CTA j owns 8 hidden units
// (32 gate rows of W_hh in SMEM, fp16 hi/lo split). One grid barrier per step.
// gates(128x32) = h(128x1024) @ Wslice^T via mma.m16n8k16 fp16->f32,
// 2 products: A_f16 * (W_hi + W_lo). h broadcast is a single fp16 fragment
// buffer (2B/elem) -> halves the L2 broadcast traffic vs bf16 hi/lo.
// K-split: warp pair (w, w+8) shares an rt tile; each does 32 of 64 k-tiles.

#define NCTA 128
#define NTHR 512
#define HID 1024
#define BSZ 128
#define KP 1032   // padded K stride (fp16 elems) for W in SMEM

#define W_BYTES (32 * KP * 2 * 2)
#define RED_BYTES (8 * 32 * 16 * 4)
#define SMEM_BYTES (W_BYTES + 512 + RED_BYTES)

// h in A-fragment layout (fp16x2 packed): [rt 0..7][kt 0..63][lane][reg 0..3]
__device__ uint32_t g_frag[2][8 * 64 * 32 * 4];
__device__ unsigned int g_bar_count = 0;
__device__ unsigned int g_bar_gen = 0;

__device__ __forceinline__ float sigf(float x) {
    return __fdividef(1.0f, 1.0f + __expf(-x));
}
__device__ __forceinline__ float tanh_f(float x) {
    return __fmaf_rn(2.0f, __fdividef(1.0f, 1.0f + __expf(-2.0f * x)), -1.0f);
}

__device__ __forceinline__ void mma_f16(float* c, const uint4& a, uint32_t b0, uint32_t b1) {
    asm volatile(
        "mma.sync.aligned.m16n8k16.row.col.f32.f16.f16.f32 "
        "{%0,%1,%2,%3},{%4,%5,%6,%7},{%8,%9},{%0,%1,%2,%3};\n"
        : "+f"(c[0]), "+f"(c[1]), "+f"(c[2]), "+f"(c[3])
        : "r"(a.x), "r"(a.y), "r"(a.z), "r"(a.w), "r"(b0), "r"(b1));
}

__device__ __forceinline__ void ldsm_x4(uint32_t& r0, uint32_t& r1, uint32_t& r2,
                                        uint32_t& r3, uint32_t saddr) {
    asm volatile("ldmatrix.sync.aligned.m8n8.x4.shared.b16 {%0,%1,%2,%3}, [%4];\n"
                 : "=r"(r0), "=r"(r1), "=r"(r2), "=r"(r3) : "r"(saddr));
}

__device__ __forceinline__ uint32_t packh2(float a, float b) {
    __half2 p = __floats2half2_rn(a, b);
    return *(uint32_t*)&p;
}

__device__ __forceinline__ void grid_barrier() {
    __threadfence();
    __syncthreads();
    if (threadIdx.x == 0) {
        volatile unsigned int* vgen = &g_bar_gen;
        unsigned int g = *vgen;
        unsigned int arrived = atomicAdd(&g_bar_count, 1u);
        if (arrived == NCTA - 1) {
            g_bar_count = 0;
            __threadfence();
            atomicExch(&g_bar_gen, g + 1u);
        } else {
            while (*vgen == g) {}
        }
        __threadfence();
    }
    __syncthreads();
}

extern __shared__ char smem_raw[];

__global__ __launch_bounds__(NTHR, 1) void decoder_kernel(
    const float* __restrict__ h0, const float* __restrict__ c0,
    const float* __restrict__ Wih, const float* __restrict__ Whh,
    const float* __restrict__ bih, const float* __restrict__ bhh,
    const float* __restrict__ Wlin, const float* __restrict__ blin,
    float* __restrict__ out, int T)
{
    __half* ws_hi = (__half*)smem_raw;                 // [32][KP]
    __half* ws_lo = ws_hi + 32 * KP;                   // [32][KP]
    float* cc0 = (float*)(smem_raw + W_BYTES);         // bias (t=0)
    float* cc1 = cc0 + 32;                             // bias + Wih[:,1]
    float* wi0 = cc1 + 32;                             // Wih[:,0]
    float* wl  = wi0 + 32;                             // Wlin slice [8]
    float* red = (float*)(smem_raw + W_BYTES + 512);   // [8][32][16] partials

    const int j    = blockIdx.x;
    const int tid  = threadIdx.x;
    const int w    = tid >> 5;
    const int wk   = w & 7;      // rt tile
    const int ks   = w >> 3;     // k-split half (0 or 1)
    const int lane = tid & 31;
    const int gi   = lane >> 2;
    const int tq   = lane & 3;

    // ---------------- init: W slice -> SMEM fp16 hi/lo ----------------
    for (int idx = tid; idx < 32 * HID; idx += NTHR) {
        int n = idx >> 10;
        int k = idx & (HID - 1);
        int row = ((n >> 3) << 10) + (j << 3) + (n & 7);
        float wv = Whh[row * HID + k];
        __half hi = __float2half_rn(wv);
        ws_hi[n * KP + k] = hi;
        ws_lo[n * KP + k] = __float2half_rn(wv - __half2float(hi));
    }
    if (tid < 32) {
        int n = tid;
        int row = ((n >> 3) << 10) + (j << 3) + (n & 7);
        float bb = bih[row] + bhh[row];
        cc0[n] = bb;
        cc1[n] = bb + Wih[row * 2 + 1];
        wi0[n] = Wih[row * 2 + 0];
    }
    if (tid < 8) wl[tid] = Wlin[(j << 3) + tid];

    // h0 -> fragment-layout buffer 0 (CTA j converts batch row j)
    for (int p = tid; p < HID / 2; p += NTHR) {
        int k0 = p << 1;
        float a = h0[j * HID + k0], b = h0[j * HID + k0 + 1];
        int rt = j >> 4, kt = k0 >> 4;
        int lanep = (j & 7) * 4 + ((k0 >> 1) & 3);
        int reg = ((j >> 3) & 1) + 2 * ((k0 >> 3) & 1);
        int idx = ((rt * 64 + kt) * 32 + lanep) * 4 + reg;
        g_frag[0][idx] = packh2(a, b);
    }
    for (int t = tid; t < T; t += NTHR) out[j * T + t] = 0.0f;

    // c-state in registers (pointwise warps ks==0 only)
    const int R0 = (wk << 4) + gi;
    const int v0 = tq << 1;
    const int u0 = (j << 3) + v0;
    float creg[4] = {0.f, 0.f, 0.f, 0.f};
    if (ks == 0) {
        creg[0] = c0[R0 * HID + u0];
        creg[1] = c0[R0 * HID + u0 + 1];
        creg[2] = c0[(R0 + 8) * HID + u0];
        creg[3] = c0[(R0 + 8) * HID + u0 + 1];
    }
    const float blin0 = blin[0];

    // ldmatrix per-lane base addresses (4 matrices: {nb,nb+1} x {k,k+8})
    const int m_   = lane >> 3;
    const int rr_  = lane & 7;
    const int nloc = ((m_ >> 1) << 3) + rr_;
    const int koff = (m_ & 1) << 3;
    const uint32_t s_hi = (uint32_t)__cvta_generic_to_shared(ws_hi);
    const uint32_t s_lo = (uint32_t)__cvta_generic_to_shared(ws_lo);
    const uint32_t sb_hi01 = s_hi + (nloc * KP + koff) * 2;
    const uint32_t sb_hi23 = sb_hi01 + 16 * KP * 2;
    const uint32_t sb_lo01 = s_lo + (nloc * KP + koff) * 2;
    const uint32_t sb_lo23 = sb_lo01 + 16 * KP * 2;

    const int kt0   = ks << 5;
    const int abase = wk * 8192 + kt0 * 128 + lane * 4;
    const int wbase = ((wk * 64 + (j >> 1)) * 32 + lane) * 4 + 2 * (j & 1);
    float* redp = red + (wk * 32 + lane) * 16;

    grid_barrier();

    // ---------------- time loop ----------------
    for (int t = 0; t < T; ++t) {
        const uint32_t* A = g_frag[t & 1];
        uint32_t* N = g_frag[(t + 1) & 1];

        // acc init: warps ks==0 carry bias + feedback; ks==1 carry zeros
        float acc[4][4];
        if (ks == 0) {
            float op0 = 0.0f, op1 = 0.0f;
            const float* cc = cc0;
            if (t > 0) {
                op0 = __ldcg(&out[R0 * T + t - 1]);
                op1 = __ldcg(&out[(R0 + 8) * T + t - 1]);
                cc = cc1;
            }
#pragma unroll
            for (int nb = 0; nb < 4; ++nb) {
                int n0 = (nb << 3) + v0;
                float b0 = cc[n0], b1 = cc[n0 + 1];
                float wa = wi0[n0], wb = wi0[n0 + 1];
                acc[nb][0] = fmaf(op0, wa, b0);
                acc[nb][1] = fmaf(op0, wb, b1);
                acc[nb][2] = fmaf(op1, wa, b0);
                acc[nb][3] = fmaf(op1, wb, b1);
            }
        } else {
#pragma unroll
            for (int nb = 0; nb < 4; ++nb)
#pragma unroll
                for (int c = 0; c < 4; ++c) acc[nb][c] = 0.0f;
        }

        // GEMM: this warp's 32 k-tiles, 2 products (W hi + W lo), fp16 A
#pragma unroll 4
        for (int i = 0; i < 32; ++i) {
            uint4 a = __ldcg((const uint4*)(A + abase + i * 128));
            uint32_t so = (kt0 + i) * 32;
            uint32_t bh0, bh1, bh2, bh3, bh4, bh5, bh6, bh7;
            uint32_t bl0, bl1, bl2, bl3, bl4, bl5, bl6, bl7;
            ldsm_x4(bh0, bh1, bh2, bh3, sb_hi01 + so);
            ldsm_x4(bh4, bh5, bh6, bh7, sb_hi23 + so);
            ldsm_x4(bl0, bl1, bl2, bl3, sb_lo01 + so);
            ldsm_x4(bl4, bl5, bl6, bl7, sb_lo23 + so);
            mma_f16(acc[0], a, bh0, bh1);
            mma_f16(acc[0], a, bl0, bl1);
            mma_f16(acc[1], a, bh2, bh3);
            mma_f16(acc[1], a, bl2, bl3);
            mma_f16(acc[2], a, bh4, bh5);
            mma_f16(acc[2], a, bl4, bl5);
            mma_f16(acc[3], a, bh6, bh7);
            mma_f16(acc[3], a, bl6, bl7);
        }

        // merge k-split partials through SMEM
        if (ks == 1) {
#pragma unroll
            for (int nb = 0; nb < 4; ++nb)
#pragma unroll
                for (int c = 0; c < 4; ++c) redp[nb * 4 + c] = acc[nb][c];
        }
        __syncthreads();

        if (ks == 0) {
#pragma unroll
            for (int nb = 0; nb < 4; ++nb)
#pragma unroll
                for (int c = 0; c < 4; ++c) acc[nb][c] += redp[nb * 4 + c];

            // pointwise LSTM update (all 4 gates local to this thread)
            float hn[4];
            float s0 = 0.0f, s1 = 0.0f;
#pragma unroll
            for (int ci = 0; ci < 4; ++ci) {
                float iv = sigf(acc[0][ci]);
                float fv = sigf(acc[1][ci]);
                float gv = tanh_f(acc[2][ci]);
                float ov = sigf(acc[3][ci]);
                float cn = fmaf(fv, creg[ci], iv * gv);
                creg[ci] = cn;
                float h = ov * tanh_f(cn);
                hn[ci] = h;
                float contrib = h * wl[v0 + (ci & 1)];
                if (ci < 2) s0 += contrib; else s1 += contrib;
            }
            *(uint2*)(N + wbase) =
                make_uint2(packh2(hn[0], hn[1]), packh2(hn[2], hn[3]));

            s0 += __shfl_xor_sync(0xffffffffu, s0, 1);
            s0 += __shfl_xor_sync(0xffffffffu, s0, 2);
            s1 += __shfl_xor_sync(0xffffffffu, s1, 1);
            s1 += __shfl_xor_sync(0xffffffffu, s1, 2);
            if (tq == 0) {
                if (j == 0) { s0 += blin0; s1 += blin0; }
                atomicAdd(&out[R0 * T + t], s0);
                atomicAdd(&out[(R0 + 8) * T + t], s1);
            }
        }

        grid_barrier();
    }
}

extern "C" void kernel_launch(void* const* d_in, const int* in_sizes, int n_in,
                              void* d_out, int out_size) {
    const float* h0   = (const float*)d_in[0];
    const float* c0   = (const float*)d_in[1];
    const float* Wih  = (const float*)d_in[2];
    const float* Whh  = (const float*)d_in[3];
    const float* bih  = (const float*)d_in[4];
    const float* bhh  = (const float*)d_in[5];
    const float* Wlin = (const float*)d_in[6];
    const float* blin = (const float*)d_in[7];
    float* out = (float*)d_out;

    int T = out_size / BSZ;
    if (T <= 0) return;

    cudaFuncSetAttribute(decoder_kernel,
                         cudaFuncAttributeMaxDynamicSharedMemorySize, SMEM_BYTES);
    decoder_kernel<<<NCTA, NTHR, SMEM_BYTES>>>(h0, c0, Wih, Whh, bih, bhh,
                                               Wlin, blin, out, T);
}

// round 10
// speedup vs baseline: 3.4669x; 1.2923x over previous
#include <cuda_runtime.h>
#include <cuda_fp16.h>
#include <cstdint>

// Decoder LSTM: B=128, H=1024, T=256, OUT=1, IN=2.
// Persistent kernel, 128 CTAs x 512 thr (16 warps). CTA j owns 8 hidden units
// (32 gate rows of W_hh in SMEM, single fp16). One grid barrier per step.
// gates(128x32) = h(128x1024) @ Wslice^T via mma.m16n8k16 fp16->f32,
// single product (A fp16, W fp16). h broadcast = fp16 fragment buffer.
// K-split: warp pair (w, w+8) shares an rt tile; each does 32 of 64 k-tiles.

#define NCTA 128
#define NTHR 512
#define HID 1024
#define BSZ 128
#define KP 1032   // padded K stride (fp16 elems) for W in SMEM

#define W_BYTES (32 * KP * 2)
#define RED_BYTES (8 * 32 * 16 * 4)
#define SMEM_BYTES (W_BYTES + 512 + RED_BYTES)

// h in A-fragment layout (fp16x2 packed): [rt 0..7][kt 0..63][lane][reg 0..3]
__device__ uint32_t g_frag[2][8 * 64 * 32 * 4];
__device__ unsigned int g_bar_count = 0;
__device__ unsigned int g_bar_gen = 0;

__device__ __forceinline__ float sigf(float x) {
    return __fdividef(1.0f, 1.0f + __expf(-x));
}
__device__ __forceinline__ float tanh_f(float x) {
    return __fmaf_rn(2.0f, __fdividef(1.0f, 1.0f + __expf(-2.0f * x)), -1.0f);
}

__device__ __forceinline__ void mma_f16(float* c, const uint4& a, uint32_t b0, uint32_t b1) {
    asm volatile(
        "mma.sync.aligned.m16n8k16.row.col.f32.f16.f16.f32 "
        "{%0,%1,%2,%3},{%4,%5,%6,%7},{%8,%9},{%0,%1,%2,%3};\n"
        : "+f"(c[0]), "+f"(c[1]), "+f"(c[2]), "+f"(c[3])
        : "r"(a.x), "r"(a.y), "r"(a.z), "r"(a.w), "r"(b0), "r"(b1));
}

__device__ __forceinline__ void ldsm_x4(uint32_t& r0, uint32_t& r1, uint32_t& r2,
                                        uint32_t& r3, uint32_t saddr) {
    asm volatile("ldmatrix.sync.aligned.m8n8.x4.shared.b16 {%0,%1,%2,%3}, [%4];\n"
                 : "=r"(r0), "=r"(r1), "=r"(r2), "=r"(r3) : "r"(saddr));
}

__device__ __forceinline__ uint32_t packh2(float a, float b) {
    __half2 p = __floats2half2_rn(a, b);
    return *(uint32_t*)&p;
}

__device__ __forceinline__ void grid_barrier() {
    __threadfence();
    __syncthreads();
    if (threadIdx.x == 0) {
        volatile unsigned int* vgen = &g_bar_gen;
        unsigned int g = *vgen;
        unsigned int arrived = atomicAdd(&g_bar_count, 1u);
        if (arrived == NCTA - 1) {
            g_bar_count = 0;
            __threadfence();
            atomicExch(&g_bar_gen, g + 1u);
        } else {
            while (*vgen == g) {}
        }
        __threadfence();
    }
    __syncthreads();
}

extern __shared__ char smem_raw[];

__global__ __launch_bounds__(NTHR, 1) void decoder_kernel(
    const float* __restrict__ h0, const float* __restrict__ c0,
    const float* __restrict__ Wih, const float* __restrict__ Whh,
    const float* __restrict__ bih, const float* __restrict__ bhh,
    const float* __restrict__ Wlin, const float* __restrict__ blin,
    float* __restrict__ out, int T)
{
    __half* ws = (__half*)smem_raw;                    // [32][KP] fp16 W slice
    float* cc0 = (float*)(smem_raw + W_BYTES);         // bias (t=0)
    float* cc1 = cc0 + 32;                             // bias + Wih[:,1]
    float* wi0 = cc1 + 32;                             // Wih[:,0]
    float* wl  = wi0 + 32;                             // Wlin slice [8]
    float* red = (float*)(smem_raw + W_BYTES + 512);   // [8][32][16] partials

    const int j    = blockIdx.x;
    const int tid  = threadIdx.x;
    const int w    = tid >> 5;
    const int wk   = w & 7;      // rt tile
    const int ks   = w >> 3;     // k-split half (0 or 1)
    const int lane = tid & 31;
    const int gi   = lane >> 2;
    const int tq   = lane & 3;

    // ---------------- init: W slice -> SMEM fp16 ----------------
    for (int idx = tid; idx < 32 * HID; idx += NTHR) {
        int n = idx >> 10;
        int k = idx & (HID - 1);
        int row = ((n >> 3) << 10) + (j << 3) + (n & 7);
        ws[n * KP + k] = __float2half_rn(Whh[row * HID + k]);
    }
    if (tid < 32) {
        int n = tid;
        int row = ((n >> 3) << 10) + (j << 3) + (n & 7);
        float bb = bih[row] + bhh[row];
        cc0[n] = bb;
        cc1[n] = bb + Wih[row * 2 + 1];
        wi0[n] = Wih[row * 2 + 0];
    }
    if (tid < 8) wl[tid] = Wlin[(j << 3) + tid];

    // h0 -> fragment-layout buffer 0 (CTA j converts batch row j)
    for (int p = tid; p < HID / 2; p += NTHR) {
        int k0 = p << 1;
        float a = h0[j * HID + k0], b = h0[j * HID + k0 + 1];
        int rt = j >> 4, kt = k0 >> 4;
        int lanep = (j & 7) * 4 + ((k0 >> 1) & 3);
        int reg = ((j >> 3) & 1) + 2 * ((k0 >> 3) & 1);
        int idx = ((rt * 64 + kt) * 32 + lanep) * 4 + reg;
        g_frag[0][idx] = packh2(a, b);
    }
    for (int t = tid; t < T; t += NTHR) out[j * T + t] = 0.0f;

    // c-state in registers (pointwise warps ks==0 only)
    const int R0 = (wk << 4) + gi;
    const int v0 = tq << 1;
    const int u0 = (j << 3) + v0;
    float creg[4] = {0.f, 0.f, 0.f, 0.f};
    if (ks == 0) {
        creg[0] = c0[R0 * HID + u0];
        creg[1] = c0[R0 * HID + u0 + 1];
        creg[2] = c0[(R0 + 8) * HID + u0];
        creg[3] = c0[(R0 + 8) * HID + u0 + 1];
    }
    const float blin0 = blin[0];

    // ldmatrix per-lane base addresses (4 matrices: {nb,nb+1} x {k,k+8})
    const int m_   = lane >> 3;
    const int rr_  = lane & 7;
    const int nloc = ((m_ >> 1) << 3) + rr_;
    const int koff = (m_ & 1) << 3;
    const uint32_t s_w = (uint32_t)__cvta_generic_to_shared(ws);
    const uint32_t sb01 = s_w + (nloc * KP + koff) * 2;
    const uint32_t sb23 = sb01 + 16 * KP * 2;

    const int kt0   = ks << 5;
    const int abase = wk * 8192 + kt0 * 128 + lane * 4;
    const int wbase = ((wk * 64 + (j >> 1)) * 32 + lane) * 4 + 2 * (j & 1);
    float* redp = red + (wk * 32 + lane) * 16;

    grid_barrier();

    // ---------------- time loop ----------------
    for (int t = 0; t < T; ++t) {
        const uint32_t* A = g_frag[t & 1];
        uint32_t* N = g_frag[(t + 1) & 1];

        // acc init: warps ks==0 carry bias + feedback; ks==1 carry zeros
        float acc[4][4];
        if (ks == 0) {
            float op0 = 0.0f, op1 = 0.0f;
            const float* cc = cc0;
            if (t > 0) {
                op0 = __ldcg(&out[R0 * T + t - 1]);
                op1 = __ldcg(&out[(R0 + 8) * T + t - 1]);
                cc = cc1;
            }
#pragma unroll
            for (int nb = 0; nb < 4; ++nb) {
                int n0 = (nb << 3) + v0;
                float b0 = cc[n0], b1 = cc[n0 + 1];
                float wa = wi0[n0], wb = wi0[n0 + 1];
                acc[nb][0] = fmaf(op0, wa, b0);
                acc[nb][1] = fmaf(op0, wb, b1);
                acc[nb][2] = fmaf(op1, wa, b0);
                acc[nb][3] = fmaf(op1, wb, b1);
            }
        } else {
#pragma unroll
            for (int nb = 0; nb < 4; ++nb)
#pragma unroll
                for (int c = 0; c < 4; ++c) acc[nb][c] = 0.0f;
        }

        // GEMM: this warp's 32 k-tiles, single fp16 product
#pragma unroll 8
        for (int i = 0; i < 32; ++i) {
            uint4 a = __ldcg((const uint4*)(A + abase + i * 128));
            uint32_t so = (kt0 + i) * 32;
            uint32_t b0, b1, b2, b3, b4, b5, b6, b7;
            ldsm_x4(b0, b1, b2, b3, sb01 + so);
            ldsm_x4(b4, b5, b6, b7, sb23 + so);
            mma_f16(acc[0], a, b0, b1);
            mma_f16(acc[1], a, b2, b3);
            mma_f16(acc[2], a, b4, b5);
            mma_f16(acc[3], a, b6, b7);
        }

        // merge k-split partials through SMEM
        if (ks == 1) {
#pragma unroll
            for (int nb = 0; nb < 4; ++nb)
#pragma unroll
                for (int c = 0; c < 4; ++c) redp[nb * 4 + c] = acc[nb][c];
        }
        __syncthreads();

        if (ks == 0) {
#pragma unroll
            for (int nb = 0; nb < 4; ++nb)
#pragma unroll
                for (int c = 0; c < 4; ++c) acc[nb][c] += redp[nb * 4 + c];

            // pointwise LSTM update (all 4 gates local to this thread)
            float hn[4];
            float s0 = 0.0f, s1 = 0.0f;
#pragma unroll
            for (int ci = 0; ci < 4; ++ci) {
                float iv = sigf(acc[0][ci]);
                float fv = sigf(acc[1][ci]);
                float gv = tanh_f(acc[2][ci]);
                float ov = sigf(acc[3][ci]);
                float cn = fmaf(fv, creg[ci], iv * gv);
                creg[ci] = cn;
                float h = ov * tanh_f(cn);
                hn[ci] = h;
                float contrib = h * wl[v0 + (ci & 1)];
                if (ci < 2) s0 += contrib; else s1 += contrib;
            }
            *(uint2*)(N + wbase) =
                make_uint2(packh2(hn[0], hn[1]), packh2(hn[2], hn[3]));

            s0 += __shfl_xor_sync(0xffffffffu, s0, 1);
            s0 += __shfl_xor_sync(0xffffffffu, s0, 2);
            s1 += __shfl_xor_sync(0xffffffffu, s1, 1);
            s1 += __shfl_xor_sync(0xffffffffu, s1, 2);
            if (tq == 0) {
                if (j == 0) { s0 += blin0; s1 += blin0; }
                atomicAdd(&out[R0 * T + t], s0);
                atomicAdd(&out[(R0 + 8) * T + t], s1);
            }
        }

        grid_barrier();
    }
}

extern "C" void kernel_launch(void* const* d_in, const int* in_sizes, int n_in,
                              void* d_out, int out_size) {
    const float* h0   = (const float*)d_in[0];
    const float* c0   = (const float*)d_in[1];
    const float* Wih  = (const float*)d_in[2];
    const float* Whh  = (const float*)d_in[3];
    const float* bih  = (const float*)d_in[4];
    const float* bhh  = (const float*)d_in[5];
    const float* Wlin = (const float*)d_in[6];
    const float* blin = (const float*)d_in[7];
    float* out = (float*)d_out;

    int T = out_size / BSZ;
    if (T <= 0) return;

    cudaFuncSetAttribute(decoder_kernel,
                         cudaFuncAttributeMaxDynamicSharedMemorySize, SMEM_BYTES);
    decoder_kernel<<<NCTA, NTHR, SMEM_BYTES>>>(h0, c0, Wih, Whh, bih, bhh,
                                               Wlin, blin, out, T);
}